// round 1
// baseline (speedup 1.0000x reference)
#include <cuda_runtime.h>
#include <cuda_bf16.h>

#define T_LEN 4096
#define E_DIM 256
#define H_DIM 10
#define G_DIM 40           // 4*H
#define O_DIM 50257

// Scratch (static device globals: no allocation allowed)
__device__ float g_xg[T_LEN * G_DIM];   // 655 KB, L2-resident
__device__ float g_hs[T_LEN * H_DIM];   // 160 KB

// ---------------------------------------------------------------------------
// Kernel 1: xg[t][r] = dot(embedding[x[t]], w_ih[r]) + b_ih[r] + b_hh[r]
// 4096 blocks x 128 threads; warp w handles gate rows [10w, 10w+10)
// ---------------------------------------------------------------------------
__global__ void __launch_bounds__(128) k_embed_gates(
    const int* __restrict__ x, const float* __restrict__ emb,
    const float* __restrict__ w_ih, const float* __restrict__ b_ih,
    const float* __restrict__ b_hh)
{
    const int t    = blockIdx.x;
    const int lane = threadIdx.x & 31;
    const int warp = threadIdx.x >> 5;        // 0..3
    const float* erow = emb + (long)x[t] * E_DIM;

    float acc[10];
#pragma unroll
    for (int r = 0; r < 10; r++) acc[r] = 0.f;

#pragma unroll
    for (int i = 0; i < E_DIM / 32; i++) {
        const int e  = lane + i * 32;
        const float ev = __ldg(erow + e);
#pragma unroll
        for (int r = 0; r < 10; r++)
            acc[r] = fmaf(ev, __ldg(w_ih + (warp * 10 + r) * E_DIM + e), acc[r]);
    }
#pragma unroll
    for (int r = 0; r < 10; r++) {
        float v = acc[r];
#pragma unroll
        for (int s = 16; s > 0; s >>= 1) v += __shfl_xor_sync(0xffffffffu, v, s);
        if (lane == 0) {
            const int row = warp * 10 + r;
            g_xg[t * G_DIM + row] = v + b_ih[row] + b_hh[row];
        }
    }
}

// ---------------------------------------------------------------------------
// Kernel 2: sequential LSTM scan. 1 block, 1 warp. Lane j < 10 owns hidden
// unit j and computes all 4 of its gates; h broadcast via shfl each step.
// w_hh kept entirely in registers. 1-step software prefetch of xg.
// ---------------------------------------------------------------------------
__device__ __forceinline__ float sigmoid_(float v) {
    return __fdividef(1.f, 1.f + __expf(-v));
}
__device__ __forceinline__ float tanh_(float v) {
    const float a = fabsf(v);
    const float e = __expf(-2.f * a);
    const float r = __fdividef(1.f - e, 1.f + e);
    return copysignf(r, v);
}

__global__ void __launch_bounds__(32) k_scan(const float* __restrict__ w_hh)
{
    const int j   = threadIdx.x;
    const bool act = (j < H_DIM);

    float w[4][H_DIM];
#pragma unroll
    for (int g = 0; g < 4; g++)
#pragma unroll
        for (int k = 0; k < H_DIM; k++)
            w[g][k] = act ? w_hh[(g * H_DIM + j) * H_DIM + k] : 0.f;

    float h = 0.f, c = 0.f;
    float cur[4], nxt[4];
#pragma unroll
    for (int g = 0; g < 4; g++)
        cur[g] = act ? g_xg[g * H_DIM + j] : 0.f;

    for (int t = 0; t < T_LEN; t++) {
        // prefetch next step's gate inputs (hides ~234cyc L2 latency)
        const int tn = (t + 1 < T_LEN) ? t + 1 : t;
#pragma unroll
        for (int g = 0; g < 4; g++)
            nxt[g] = act ? g_xg[tn * G_DIM + g * H_DIM + j] : 0.f;

        float hv[H_DIM];
#pragma unroll
        for (int k = 0; k < H_DIM; k++)
            hv[k] = __shfl_sync(0xffffffffu, h, k);

        float gi = cur[0], gf = cur[1], gc = cur[2], go = cur[3];
#pragma unroll
        for (int k = 0; k < H_DIM; k++) {
            gi = fmaf(hv[k], w[0][k], gi);
            gf = fmaf(hv[k], w[1][k], gf);
            gc = fmaf(hv[k], w[2][k], gc);
            go = fmaf(hv[k], w[3][k], go);
        }
        const float i_ = sigmoid_(gi);
        const float f_ = sigmoid_(gf);
        const float g_ = tanh_(gc);
        const float o_ = sigmoid_(go);
        c = f_ * c + i_ * g_;
        h = o_ * tanh_(c);

        if (act) g_hs[t * H_DIM + j] = h;
#pragma unroll
        for (int g = 0; g < 4; g++) cur[g] = nxt[g];
    }
}

// ---------------------------------------------------------------------------
// Kernel 3: logits[t][o] = dot(hs[t], W_out[o]) + b_out[o]
// HBM-store bound (823 MB). Tile: 64 timesteps x 1024 vocab per block.
// Each thread holds 4 W rows (40 regs) + bias, hs tile in shared.
// Grid: (ceil(O/1024), T/64); 256 threads.
// ---------------------------------------------------------------------------
__global__ void __launch_bounds__(256) k_out(
    const float* __restrict__ W, const float* __restrict__ b,
    float* __restrict__ out)
{
    const int t0    = blockIdx.y * 64;
    const int obase = blockIdx.x * 1024 + threadIdx.x;

    __shared__ float hsh[64 * H_DIM];
    for (int i = threadIdx.x; i < 64 * H_DIM; i += 256)
        hsh[i] = g_hs[t0 * H_DIM + i];

    float w[4][H_DIM];
    float bb[4];
    bool valid[4];
#pragma unroll
    for (int q = 0; q < 4; q++) {
        const int o = obase + q * 256;
        valid[q] = (o < O_DIM);
        bb[q] = valid[q] ? __ldg(b + o) : 0.f;
#pragma unroll
        for (int k = 0; k < H_DIM; k++)
            w[q][k] = valid[q] ? __ldg(W + (long)o * H_DIM + k) : 0.f;
    }
    __syncthreads();

    for (int tt = 0; tt < 64; tt++) {
        float hv[H_DIM];
#pragma unroll
        for (int k = 0; k < H_DIM; k++) hv[k] = hsh[tt * H_DIM + k];
        const long rowoff = (long)(t0 + tt) * O_DIM;
#pragma unroll
        for (int q = 0; q < 4; q++) {
            float acc = bb[q];
#pragma unroll
            for (int k = 0; k < H_DIM; k++)
                acc = fmaf(hv[k], w[q][k], acc);
            if (valid[q]) out[rowoff + obase + q * 256] = acc;
        }
    }
}

// ---------------------------------------------------------------------------
extern "C" void kernel_launch(void* const* d_in, const int* in_sizes, int n_in,
                              void* d_out, int out_size)
{
    const int*   x    = (const int*)  d_in[0];
    const float* emb  = (const float*)d_in[1];
    const float* w_ih = (const float*)d_in[2];
    const float* w_hh = (const float*)d_in[3];
    const float* b_ih = (const float*)d_in[4];
    const float* b_hh = (const float*)d_in[5];
    const float* Wout = (const float*)d_in[6];
    const float* bout = (const float*)d_in[7];
    float* out = (float*)d_out;

    k_embed_gates<<<T_LEN, 128>>>(x, emb, w_ih, b_ih, b_hh);
    k_scan<<<1, 32>>>(w_hh);
    dim3 grid((O_DIM + 1023) / 1024, T_LEN / 64);
    k_out<<<grid, 256>>>(Wout, bout, out);
}

// round 2
// speedup vs baseline: 1.4279x; 1.4279x over previous
#include <cuda_runtime.h>
#include <cuda_bf16.h>

#define T_LEN 4096
#define E_DIM 256
#define H_DIM 10
#define G_DIM 40           // 4*H
#define O_DIM 50257
#define NB    128          // fused-kernel grid
#define OC_TILES 50        // ceil(O_DIM/1024)
#define TC_TILES 64        // T_LEN/64
#define N_TILES  (OC_TILES * TC_TILES)

// Scratch (static device globals: no allocation allowed)
// g_xg layout: [t][unit j][gate g]  (g fastest) -> one float4 per (t, j)
__device__ float g_xg[(T_LEN + 8) * G_DIM];   // padded for prefetch overrun
__device__ float g_hs[T_LEN * H_DIM];
__device__ int   g_progress;

// ---------------------------------------------------------------------------
// Kernel 1: xg[t][j][g] = dot(embedding[x[t]], w_ih[g*10+j]) + b_ih + b_hh
// 4096 blocks x 128 threads; warp w == gate g, handles units j=0..9.
// Also resets the producer/consumer progress counter for this replay.
// ---------------------------------------------------------------------------
__global__ void __launch_bounds__(128) k_embed_gates(
    const int* __restrict__ x, const float* __restrict__ emb,
    const float* __restrict__ w_ih, const float* __restrict__ b_ih,
    const float* __restrict__ b_hh)
{
    if (blockIdx.x == 0 && threadIdx.x == 0) g_progress = 0;

    const int t    = blockIdx.x;
    const int lane = threadIdx.x & 31;
    const int gate = threadIdx.x >> 5;        // 0..3
    const float* erow = emb + (long)x[t] * E_DIM;

    float acc[10];
#pragma unroll
    for (int r = 0; r < 10; r++) acc[r] = 0.f;

#pragma unroll
    for (int i = 0; i < E_DIM / 32; i++) {
        const int e  = lane + i * 32;
        const float ev = __ldg(erow + e);
#pragma unroll
        for (int r = 0; r < 10; r++)
            acc[r] = fmaf(ev, __ldg(w_ih + (gate * 10 + r) * E_DIM + e), acc[r]);
    }
#pragma unroll
    for (int r = 0; r < 10; r++) {
        float v = acc[r];
#pragma unroll
        for (int s = 16; s > 0; s >>= 1) v += __shfl_xor_sync(0xffffffffu, v, s);
        if (lane == 0) {
            const int row = gate * 10 + r;
            // transposed layout: [t][unit r][gate]
            g_xg[t * G_DIM + r * 4 + gate] = v + b_ih[row] + b_hh[row];
        }
    }
}

// ---------------------------------------------------------------------------
// Activations: accurate (EX2 + RCP), minimal chain length.
// ---------------------------------------------------------------------------
__device__ __forceinline__ float sig_(float v) {
    const float e = __expf(-v);                 // FMUL + MUFU.EX2
    return __fdividef(1.f, 1.f + e);            // FADD + MUFU.RCP
}
__device__ __forceinline__ float th_(float v) {
    const float vc = fmaxf(v, -40.f);           // avoid exp overflow -> NaN
    const float e  = __expf(-2.f * vc);
    return (1.f - e) * __fdividef(1.f, 1.f + e);
}

// ---------------------------------------------------------------------------
// Fused kernel:
//   block 0 / warp 0 : sequential LSTM scan, publishes progress per 64 steps
//   blocks 1..NB-1   : stream output tiles (64 t x 1024 vocab) as hs arrives
// ---------------------------------------------------------------------------
__global__ void __launch_bounds__(256) k_fused(
    const float* __restrict__ w_hh,
    const float* __restrict__ W, const float* __restrict__ bo,
    float* __restrict__ out)
{
    if (blockIdx.x == 0) {
        // ============================ PRODUCER ============================
        if (threadIdx.x >= 32) return;
        const int j   = threadIdx.x;
        const int jj  = (j < H_DIM) ? j : 0;
        const bool act = (j < H_DIM);

        float w0[H_DIM], w1[H_DIM], w2[H_DIM], w3[H_DIM];
#pragma unroll
        for (int k = 0; k < H_DIM; k++) {
            w0[k] = w_hh[(0 * H_DIM + jj) * H_DIM + k];
            w1[k] = w_hh[(1 * H_DIM + jj) * H_DIM + k];
            w2[k] = w_hh[(2 * H_DIM + jj) * H_DIM + k];
            w3[k] = w_hh[(3 * H_DIM + jj) * H_DIM + k];
        }

        const float4* __restrict__ xg4 = (const float4*)g_xg;
        float4 pA = xg4[0 * H_DIM + jj];
        float4 pB = xg4[1 * H_DIM + jj];
        float4 pC = xg4[2 * H_DIM + jj];
        float4 pD = xg4[3 * H_DIM + jj];

        float h = 0.f, c = 0.f;

#define LSTM_STEP(P, TIDX)                                                   \
        do {                                                                 \
            float hv[H_DIM];                                                 \
            _Pragma("unroll")                                                \
            for (int k = 0; k < H_DIM; k++)                                  \
                hv[k] = __shfl_sync(0xffffffffu, h, k);                      \
            float a0 = P.x, a1 = 0.f, b0 = P.y, b1 = 0.f;                    \
            float c0 = P.z, c1 = 0.f, d0 = P.w, d1 = 0.f;                    \
            _Pragma("unroll")                                                \
            for (int k = 0; k < H_DIM; k += 2) {                             \
                a0 = fmaf(hv[k], w0[k], a0); a1 = fmaf(hv[k+1], w0[k+1], a1);\
                b0 = fmaf(hv[k], w1[k], b0); b1 = fmaf(hv[k+1], w1[k+1], b1);\
                c0 = fmaf(hv[k], w2[k], c0); c1 = fmaf(hv[k+1], w2[k+1], c1);\
                d0 = fmaf(hv[k], w3[k], d0); d1 = fmaf(hv[k+1], w3[k+1], d1);\
            }                                                                \
            const float i_ = sig_(a0 + a1);                                  \
            const float f_ = sig_(b0 + b1);                                  \
            const float g_ = th_(c0 + c1);                                   \
            const float o_ = sig_(d0 + d1);                                  \
            c = fmaf(f_, c, i_ * g_);                                        \
            h = o_ * th_(c);                                                 \
            if (act) g_hs[(TIDX) * H_DIM + j] = h;                           \
        } while (0)

        for (int tb = 0; tb < T_LEN; tb += 64) {
#pragma unroll 1
            for (int t = tb; t < tb + 64; t += 4) {
                LSTM_STEP(pA, t + 0);  pA = xg4[(t + 4) * H_DIM + jj];
                LSTM_STEP(pB, t + 1);  pB = xg4[(t + 5) * H_DIM + jj];
                LSTM_STEP(pC, t + 2);  pC = xg4[(t + 6) * H_DIM + jj];
                LSTM_STEP(pD, t + 3);  pD = xg4[(t + 7) * H_DIM + jj];
            }
            __syncwarp();
            if (j == 0) {
                __threadfence();
                int done = tb + 64;
                asm volatile("st.release.gpu.b32 [%0], %1;"
                             :: "l"(&g_progress), "r"(done) : "memory");
            }
        }
#undef LSTM_STEP
        return;
    }

    // ============================== CONSUMERS ==============================
    const int tid = threadIdx.x;
    __shared__ float hsh[64 * H_DIM];

    for (int tile = blockIdx.x - 1; tile < N_TILES; tile += NB - 1) {
        const int tc = tile / OC_TILES;
        const int oc = tile % OC_TILES;
        const int need = (tc + 1) * 64;

        // every thread acquires progress (orders its subsequent g_hs loads)
        int p;
        while (true) {
            asm volatile("ld.acquire.gpu.b32 %0, [%1];"
                         : "=r"(p) : "l"(&g_progress) : "memory");
            if (p >= need) break;
            __nanosleep(128);
        }

        __syncthreads();   // protect smem from previous tile's readers
        for (int i = tid; i < 64 * H_DIM; i += 256)
            hsh[i] = g_hs[tc * 64 * H_DIM + i];
        __syncthreads();

        const int obase = oc * 1024 + tid;
        float w[4][H_DIM];
        float bb[4];
        bool  valid[4];
#pragma unroll
        for (int q = 0; q < 4; q++) {
            const int o = obase + q * 256;
            valid[q] = (o < O_DIM);
            bb[q] = valid[q] ? __ldg(bo + o) : 0.f;
#pragma unroll
            for (int k = 0; k < H_DIM; k++)
                w[q][k] = valid[q] ? __ldg(W + (long)o * H_DIM + k) : 0.f;
        }

        const int t0 = tc * 64;
        for (int tt = 0; tt < 64; tt++) {
            float hv[H_DIM];
#pragma unroll
            for (int k = 0; k < H_DIM; k++) hv[k] = hsh[tt * H_DIM + k];
            const long rowoff = (long)(t0 + tt) * O_DIM;
#pragma unroll
            for (int q = 0; q < 4; q++) {
                float acc = bb[q];
#pragma unroll
                for (int k = 0; k < H_DIM; k++)
                    acc = fmaf(hv[k], w[q][k], acc);
                if (valid[q]) out[rowoff + obase + q * 256] = acc;
            }
        }
    }
}

// ---------------------------------------------------------------------------
extern "C" void kernel_launch(void* const* d_in, const int* in_sizes, int n_in,
                              void* d_out, int out_size)
{
    const int*   x    = (const int*)  d_in[0];
    const float* emb  = (const float*)d_in[1];
    const float* w_ih = (const float*)d_in[2];
    const float* w_hh = (const float*)d_in[3];
    const float* b_ih = (const float*)d_in[4];
    const float* b_hh = (const float*)d_in[5];
    const float* Wout = (const float*)d_in[6];
    const float* bout = (const float*)d_in[7];
    float* out = (float*)d_out;

    k_embed_gates<<<T_LEN, 128>>>(x, emb, w_ih, b_ih, b_hh);
    k_fused<<<NB, 256>>>(w_hh, Wout, bout, out);
}

// round 4
// speedup vs baseline: 1.7479x; 1.2241x over previous
#include <cuda_runtime.h>
#include <cuda_bf16.h>

#define T_LEN 4096
#define E_DIM 256
#define H_DIM 10
#define G_DIM 40           // 4*H
#define O_DIM 50257
#define NB    128          // fused-kernel grid
#define OC_TILES 50        // ceil(O_DIM/1024)
#define TC_TILES 64        // T_LEN/64
#define N_TILES  (OC_TILES * TC_TILES)

// Scratch (static device globals: no allocation allowed)
// g_xg layout: [t][unit j][gate g]  (g fastest) -> one float4 per (t, j)
__device__ float g_xg[(T_LEN + 8) * G_DIM];   // padded for prefetch overrun
__device__ float g_hs[T_LEN * H_DIM];
__device__ int   g_progress;

// ---------------------------------------------------------------------------
// packed f32x2 + HW tanh helpers
// ---------------------------------------------------------------------------
typedef unsigned long long u64;

__device__ __forceinline__ u64 pack2_(float lo, float hi) {
    u64 r; asm("mov.b64 %0, {%1, %2};" : "=l"(r) : "f"(lo), "f"(hi)); return r;
}
__device__ __forceinline__ void unpack2_(u64 v, float& lo, float& hi) {
    asm("mov.b64 {%0, %1}, %2;" : "=f"(lo), "=f"(hi) : "l"(v));
}
__device__ __forceinline__ u64 fma2_(u64 a, u64 b, u64 c) {
    u64 d; asm("fma.rn.f32x2 %0, %1, %2, %3;" : "=l"(d) : "l"(a), "l"(b), "l"(c));
    return d;
}
__device__ __forceinline__ u64 add2_(u64 a, u64 b) {
    u64 d; asm("add.rn.f32x2 %0, %1, %2;" : "=l"(d) : "l"(a), "l"(b));
    return d;
}
__device__ __forceinline__ float tanhap_(float x) {
    float y; asm("tanh.approx.f32 %0, %1;" : "=f"(y) : "f"(x)); return y;
}
__device__ __forceinline__ float sigap_(float x) {
    return fmaf(0.5f, tanhap_(0.5f * x), 0.5f);
}

// ---------------------------------------------------------------------------
// Kernel 1: xg[t][j][g] = dot(embedding[x[t]], w_ih[g*10+j]) + b_ih + b_hh
// transposed layout so the scan does one LDG.128 per (t, unit).
// ---------------------------------------------------------------------------
__global__ void __launch_bounds__(128) k_embed_gates(
    const int* __restrict__ x, const float* __restrict__ emb,
    const float* __restrict__ w_ih, const float* __restrict__ b_ih,
    const float* __restrict__ b_hh)
{
    if (blockIdx.x == 0 && threadIdx.x == 0) g_progress = 0;

    const int t    = blockIdx.x;
    const int lane = threadIdx.x & 31;
    const int gate = threadIdx.x >> 5;        // 0..3
    const float* erow = emb + (long)x[t] * E_DIM;

    float acc[10];
#pragma unroll
    for (int r = 0; r < 10; r++) acc[r] = 0.f;

#pragma unroll
    for (int i = 0; i < E_DIM / 32; i++) {
        const int e  = lane + i * 32;
        const float ev = __ldg(erow + e);
#pragma unroll
        for (int r = 0; r < 10; r++)
            acc[r] = fmaf(ev, __ldg(w_ih + (gate * 10 + r) * E_DIM + e), acc[r]);
    }
#pragma unroll
    for (int r = 0; r < 10; r++) {
        float v = acc[r];
#pragma unroll
        for (int s = 16; s > 0; s >>= 1) v += __shfl_xor_sync(0xffffffffu, v, s);
        if (lane == 0) {
            const int row = gate * 10 + r;
            g_xg[t * G_DIM + r * 4 + gate] = v + b_ih[row] + b_hh[row];
        }
    }
}

// ---------------------------------------------------------------------------
// Fused kernel:
//   block 0 / warp 0 : sequential LSTM scan, publishes progress per 64 steps
//   blocks 1..NB-1   : stream output tiles (64 t x 1024 vocab) as hs arrives
// ---------------------------------------------------------------------------
__global__ void __launch_bounds__(256) k_fused(
    const float* __restrict__ w_hh,
    const float* __restrict__ W, const float* __restrict__ bo,
    float* __restrict__ out)
{
    if (blockIdx.x == 0) {
        // ============================ PRODUCER ============================
        if (threadIdx.x >= 32) return;
        const int j   = threadIdx.x;
        const int jj  = (j < H_DIM) ? j : 0;
        const bool act = (j < H_DIM);

        // packed recurrent weights: w01[k] = (w_i[k], w_f[k]), w23 = (w_g, w_o)
        u64 w01[H_DIM], w23[H_DIM];
#pragma unroll
        for (int k = 0; k < H_DIM; k++) {
            w01[k] = pack2_(w_hh[(0 * H_DIM + jj) * H_DIM + k],
                            w_hh[(1 * H_DIM + jj) * H_DIM + k]);
            w23[k] = pack2_(w_hh[(2 * H_DIM + jj) * H_DIM + k],
                            w_hh[(3 * H_DIM + jj) * H_DIM + k]);
        }

        const float4* __restrict__ xg4 = (const float4*)g_xg;
        float4 pA = xg4[0 * H_DIM + jj];
        float4 pB = xg4[1 * H_DIM + jj];
        float4 pC = xg4[2 * H_DIM + jj];
        float4 pD = xg4[3 * H_DIM + jj];

        float h = 0.f, c = 0.f;

#define LSTM_STEP(P, TIDX)                                                    \
        do {                                                                  \
            u64 hp[H_DIM];                                                    \
            _Pragma("unroll")                                                 \
            for (int k = 0; k < H_DIM; k++) {                                 \
                const float hk = __shfl_sync(0xffffffffu, h, k);              \
                hp[k] = pack2_(hk, hk);                                       \
            }                                                                 \
            u64 aI = pack2_(P.x, P.y), bI = 0ull;                             \
            u64 aG = pack2_(P.z, P.w), bG = 0ull;                             \
            _Pragma("unroll")                                                 \
            for (int k = 0; k < H_DIM; k += 2) {                              \
                aI = fma2_(hp[k], w01[k], aI);                                \
                bI = fma2_(hp[k + 1], w01[k + 1], bI);                        \
                aG = fma2_(hp[k], w23[k], aG);                                \
                bG = fma2_(hp[k + 1], w23[k + 1], bG);                        \
            }                                                                 \
            float gi, gf, gg, go;                                             \
            unpack2_(add2_(aI, bI), gi, gf);                                  \
            unpack2_(add2_(aG, bG), gg, go);                                  \
            const float i_ = sigap_(gi);                                      \
            const float f_ = sigap_(gf);                                      \
            const float g_ = tanhap_(gg);                                     \
            const float o_ = sigap_(go);                                      \
            c = fmaf(f_, c, i_ * g_);                                         \
            h = o_ * tanhap_(c);                                              \
            if (act) g_hs[(TIDX) * H_DIM + j] = h;                            \
        } while (0)

        for (int tb = 0; tb < T_LEN; tb += 64) {
#pragma unroll 1
            for (int t = tb; t < tb + 64; t += 4) {
                LSTM_STEP(pA, t + 0);  pA = xg4[(t + 4) * H_DIM + jj];
                LSTM_STEP(pB, t + 1);  pB = xg4[(t + 5) * H_DIM + jj];
                LSTM_STEP(pC, t + 2);  pC = xg4[(t + 6) * H_DIM + jj];
                LSTM_STEP(pD, t + 3);  pD = xg4[(t + 7) * H_DIM + jj];
            }
            __syncwarp();                         // publish lanes' h stores
            if (j == 0) {
                int done = tb + 64;               // release orders prior writes
                asm volatile("st.release.gpu.b32 [%0], %1;"
                             :: "l"(&g_progress), "r"(done) : "memory");
            }
        }
#undef LSTM_STEP
        return;
    }

    // ============================== CONSUMERS ==============================
    const int tid = threadIdx.x;
    __shared__ float hsh[64 * H_DIM];

    for (int tile = blockIdx.x - 1; tile < N_TILES; tile += NB - 1) {
        const int tc = tile / OC_TILES;
        const int oc = tile % OC_TILES;
        const int need = (tc + 1) * 64;

        // preload this tile's W rows + bias while (possibly) waiting
        const int obase = oc * 1024 + tid;
        float w[4][H_DIM];
        float bb[4];
        bool  valid[4];
#pragma unroll
        for (int q = 0; q < 4; q++) {
            const int o = obase + q * 256;
            valid[q] = (o < O_DIM);
            bb[q] = valid[q] ? __ldg(bo + o) : 0.f;
#pragma unroll
            for (int k = 0; k < H_DIM; k++)
                w[q][k] = valid[q] ? __ldg(W + (long)o * H_DIM + k) : 0.f;
        }

        // single-thread acquire-poll, then block-wide barrier (sync provides
        // the intra-block happens-before after t0's acquire)
        __syncthreads();   // protect smem reuse from previous tile
        if (tid == 0) {
            int p;
            while (true) {
                asm volatile("ld.acquire.gpu.b32 %0, [%1];"
                             : "=r"(p) : "l"(&g_progress) : "memory");
                if (p >= need) break;
                __nanosleep(256);
            }
        }
        __syncthreads();

        for (int i = tid; i < 64 * H_DIM; i += 256)
            hsh[i] = g_hs[tc * 64 * H_DIM + i];
        __syncthreads();

        const int t0 = tc * 64;
        for (int tt = 0; tt < 64; tt++) {
            float hv[H_DIM];
#pragma unroll
            for (int k = 0; k < H_DIM; k++) hv[k] = hsh[tt * H_DIM + k];
            const long rowoff = (long)(t0 + tt) * O_DIM;
#pragma unroll
            for (int q = 0; q < 4; q++) {
                float acc = bb[q];
#pragma unroll
                for (int k = 0; k < H_DIM; k++)
                    acc = fmaf(hv[k], w[q][k], acc);
                if (valid[q]) out[rowoff + obase + q * 256] = acc;
            }
        }
    }
}

// ---------------------------------------------------------------------------
extern "C" void kernel_launch(void* const* d_in, const int* in_sizes, int n_in,
                              void* d_out, int out_size)
{
    const int*   x    = (const int*)  d_in[0];
    const float* emb  = (const float*)d_in[1];
    const float* w_ih = (const float*)d_in[2];
    const float* w_hh = (const float*)d_in[3];
    const float* b_ih = (const float*)d_in[4];
    const float* b_hh = (const float*)d_in[5];
    const float* Wout = (const float*)d_in[6];
    const float* bout = (const float*)d_in[7];
    float* out = (float*)d_out;

    k_embed_gates<<<T_LEN, 128>>>(x, emb, w_ih, b_ih, b_hh);
    k_fused<<<NB, 256>>>(w_hh, Wout, bout, out);
}